// round 2
// baseline (speedup 1.0000x reference)
#include <cuda_runtime.h>
#include <math.h>

#define NMAX 50000
#define EMAX 800000

// ---------------- scratch (static device memory) ----------------
__device__ float g_dinv[NMAX];
__device__ int   g_deg[NMAX];
__device__ int   g_off[NMAX + 1];
__device__ int   g_cur[NMAX];
__device__ int   g_src[EMAX];
__device__ int   g_dst[EMAX];
__device__ int   g_csr_src[EMAX];
__device__ float g_csr_w[EMAX];
__device__ float g_h1[(size_t)NMAX * 128];      // x @ W1
__device__ float g_hr[(size_t)NMAX * 128];      // relu(agg1 + b1)
__device__ float g_h2[(size_t)NMAX * 16];       // g_hr @ W2
__device__ int   g_is64;

// ---------------- f32x2 packed math helpers ----------------
__device__ __forceinline__ unsigned long long pk2(float a, float b) {
    unsigned long long r;
    asm("mov.b64 %0, {%1, %2};" : "=l"(r) : "f"(a), "f"(b));
    return r;
}
__device__ __forceinline__ float2 up2(unsigned long long v) {
    float2 r;
    asm("mov.b64 {%0, %1}, %2;" : "=f"(r.x), "=f"(r.y) : "l"(v));
    return r;
}
__device__ __forceinline__ unsigned long long ffma2(unsigned long long a,
                                                    unsigned long long b,
                                                    unsigned long long c) {
    unsigned long long d;
    asm("fma.rn.f32x2 %0, %1, %2, %3;" : "=l"(d) : "l"(a), "l"(b), "l"(c));
    return d;
}

// ---------------- init: zero degree counters + dtype detect (block 0) ----------------
__global__ void k_init(const int* __restrict__ ei, int n) {
    int i = blockIdx.x * blockDim.x + threadIdx.x;
    if (i < n) g_deg[i] = 0;
    if (blockIdx.x == 0) {
        // int64 edge_index (little-endian, values < 50000) has all odd 32-bit words zero
        int v = ei[2 * threadIdx.x + 1];
        int any = __syncthreads_or(v != 0);
        if (threadIdx.x == 0) g_is64 = any ? 0 : 1;
    }
}

// ---------------- convert edges + count in-degree ----------------
__global__ void k_convert_deg(const int* __restrict__ ei, int E) {
    int e = blockIdx.x * blockDim.x + threadIdx.x;
    if (e >= E) return;
    int s, d;
    if (g_is64) { s = ei[2 * e]; d = ei[2 * E + 2 * e]; }
    else        { s = ei[e];     d = ei[E + e]; }
    g_src[e] = s; g_dst[e] = d;
    atomicAdd(&g_deg[d], 1);
}

// ---------------- single-block exclusive scan of degrees (+ dinv) ----------------
__global__ __launch_bounds__(1024) void k_scan(int n) {
    __shared__ int wsum[32];
    __shared__ int carry_s;
    int tid = threadIdx.x, lane = tid & 31, wid = tid >> 5;
    if (tid == 0) carry_s = 0;
    __syncthreads();
    for (int base = 0; base < n; base += 1024) {
        int i = base + tid;
        int orig = (i < n) ? g_deg[i] : 0;
        int v = orig;
#pragma unroll
        for (int o = 1; o < 32; o <<= 1) {
            int t = __shfl_up_sync(0xffffffffu, v, o);
            if (lane >= o) v += t;
        }
        if (lane == 31) wsum[wid] = v;
        __syncthreads();
        if (wid == 0) {
            int s = wsum[lane];
#pragma unroll
            for (int o = 1; o < 32; o <<= 1) {
                int t = __shfl_up_sync(0xffffffffu, s, o);
                if (lane >= o) s += t;
            }
            wsum[lane] = s;
        }
        __syncthreads();
        if (i < n) {
            int excl = carry_s + (wid ? wsum[wid - 1] : 0) + v - orig;
            g_off[i] = excl;
            g_cur[i] = excl;
            g_dinv[i] = rsqrtf((float)orig + 1.0f);  // +1 self-loop; always >= 1
        }
        __syncthreads();
        if (tid == 0) carry_s += wsum[31];
        __syncthreads();
    }
    if (tid == 0) g_off[n] = carry_s;
}

// ---------------- place edges into CSR buckets (with precomputed weight) ----------------
__global__ void k_place(int E) {
    int e = blockIdx.x * blockDim.x + threadIdx.x;
    if (e >= E) return;
    int s = g_src[e], d = g_dst[e];
    int slot = atomicAdd(&g_cur[d], 1);
    g_csr_src[slot] = s;
    g_csr_w[slot] = g_dinv[s] * g_dinv[d];
}

// ---------------- GEMM1: h1 = x @ W1, 8x8 register tiles, packed f32x2 FFMA ----------------
// Block = 128 threads -> 64 rows x 128 cols per block. K processed in 4 chunks of 32.
__global__ __launch_bounds__(128) void k_gemm1(const float* __restrict__ x,
                                               const float* __restrict__ W,
                                               int n) {
    __shared__ float ws[32][128];      // 16 KB: K-chunk of W1
    __shared__ float xs[32][68];       // transposed x-tile xs[k][row], padded
    int tid = threadIdx.x;
    int row0 = blockIdx.x * 64;
    int tr = tid >> 4;                 // 0..7  row group (8 rows)
    int tc = tid & 15;                 // 0..15 col group (8 cols)
    unsigned long long acc[8][4];
#pragma unroll
    for (int r = 0; r < 8; ++r)
#pragma unroll
        for (int j = 0; j < 4; ++j) acc[r][j] = 0ull;

    for (int kc = 0; kc < 4; ++kc) {
        __syncthreads();
        // load W chunk: 32x128 floats, float4, coalesced
        for (int i = tid * 4; i < 32 * 128; i += 128 * 4)
            *(float4*)(&ws[0][0] + i) = *(const float4*)(W + kc * 32 * 128 + i);
        // load x chunk transposed: 64 rows x 32 k
        for (int i = tid; i < 64 * 32; i += 128) {
            int r = i >> 5, k = i & 31;
            int gr = row0 + r;
            xs[k][r] = (gr < n) ? x[(size_t)gr * 128 + kc * 32 + k] : 0.0f;
        }
        __syncthreads();
#pragma unroll 4
        for (int k = 0; k < 32; ++k) {
            float4 xa = *(const float4*)&xs[k][tr * 8];
            float4 xb = *(const float4*)&xs[k][tr * 8 + 4];
            float4 wa = *(const float4*)&ws[k][tc * 8];
            float4 wb = *(const float4*)&ws[k][tc * 8 + 4];
            unsigned long long wp[4] = { pk2(wa.x, wa.y), pk2(wa.z, wa.w),
                                         pk2(wb.x, wb.y), pk2(wb.z, wb.w) };
            unsigned long long xd[8] = { pk2(xa.x, xa.x), pk2(xa.y, xa.y),
                                         pk2(xa.z, xa.z), pk2(xa.w, xa.w),
                                         pk2(xb.x, xb.x), pk2(xb.y, xb.y),
                                         pk2(xb.z, xb.z), pk2(xb.w, xb.w) };
#pragma unroll
            for (int r = 0; r < 8; ++r)
#pragma unroll
                for (int j = 0; j < 4; ++j)
                    acc[r][j] = ffma2(xd[r], wp[j], acc[r][j]);
        }
    }
#pragma unroll
    for (int r = 0; r < 8; ++r) {
        int gr = row0 + tr * 8 + r;
        if (gr >= n) continue;
        float2 p0 = up2(acc[r][0]), p1 = up2(acc[r][1]);
        float2 p2 = up2(acc[r][2]), p3 = up2(acc[r][3]);
        float* dst = g_h1 + (size_t)gr * 128 + tc * 8;
        *(float4*)dst       = make_float4(p0.x, p0.y, p1.x, p1.y);
        *(float4*)(dst + 4) = make_float4(p2.x, p2.y, p3.x, p3.y);
    }
}

// ---------------- layer-1 CSR gather: warp per node, fused self-loop + b1 + relu ----------------
__global__ __launch_bounds__(256) void k_gather1(const float* __restrict__ b1, int n) {
    int node = (blockIdx.x * blockDim.x + threadIdx.x) >> 5;
    if (node >= n) return;
    int lane = threadIdx.x & 31;
    int c = lane << 2;
    float di = g_dinv[node];
    float4 acc = *(const float4*)(g_h1 + (size_t)node * 128 + c);
    float w0 = di * di;
    acc.x *= w0; acc.y *= w0; acc.z *= w0; acc.w *= w0;
    int e0 = g_off[node], e1 = g_off[node + 1];
    for (int e = e0; e < e1; ++e) {
        int s = g_csr_src[e];
        float wt = g_csr_w[e];
        float4 v = *(const float4*)(g_h1 + (size_t)s * 128 + c);
        acc.x += v.x * wt; acc.y += v.y * wt; acc.z += v.z * wt; acc.w += v.w * wt;
    }
    float4 b = *(const float4*)(b1 + c);
    float4 o = make_float4(fmaxf(acc.x + b.x, 0.0f), fmaxf(acc.y + b.y, 0.0f),
                           fmaxf(acc.z + b.z, 0.0f), fmaxf(acc.w + b.w, 0.0f));
    *(float4*)(g_hr + (size_t)node * 128 + c) = o;
}

// ---------------- GEMM2: h2 = g_hr @ W2 (128 -> 16), one row per thread ----------------
__global__ __launch_bounds__(256) void k_gemm2(const float* __restrict__ W2, int n) {
    __shared__ float wt[16][128];   // transposed: wt[c][k] = W2[k*16+c]
    int tid = threadIdx.x;
    for (int i = tid; i < 2048; i += 256) wt[i & 15][i >> 4] = W2[i];
    __syncthreads();
    int row = blockIdx.x * 256 + tid;
    if (row >= n) return;
    float acc[16];
#pragma unroll
    for (int c = 0; c < 16; ++c) acc[c] = 0.0f;
    const float* xr = g_hr + (size_t)row * 128;
#pragma unroll 4
    for (int k = 0; k < 128; k += 4) {
        float4 xv = *(const float4*)(xr + k);
#pragma unroll
        for (int c = 0; c < 16; ++c) {
            float4 wv = *(const float4*)&wt[c][k];
            acc[c] += xv.x * wv.x + xv.y * wv.y + xv.z * wv.z + xv.w * wv.w;
        }
    }
    float* dst = g_h2 + (size_t)row * 16;
#pragma unroll
    for (int j = 0; j < 4; ++j)
        *(float4*)(dst + 4 * j) = make_float4(acc[4*j], acc[4*j+1], acc[4*j+2], acc[4*j+3]);
}

// ---------------- layer-2 CSR gather + b2 + log_softmax (4 lanes per node) ----------------
__global__ __launch_bounds__(256) void k_gather2(float* __restrict__ out,
                                                 const float* __restrict__ b2, int n) {
    int idx = blockIdx.x * blockDim.x + threadIdx.x;
    int node = idx >> 2;
    if (node >= n) return;          // n*4 is a multiple of 32: whole warps exit
    int q = (idx & 3) << 2;
    float di = g_dinv[node];
    float w0 = di * di;
    float4 acc = *(const float4*)(g_h2 + (size_t)node * 16 + q);
    acc.x *= w0; acc.y *= w0; acc.z *= w0; acc.w *= w0;
    int e0 = g_off[node], e1 = g_off[node + 1];
    for (int e = e0; e < e1; ++e) {
        int s = g_csr_src[e];
        float wt = g_csr_w[e];
        float4 v = *(const float4*)(g_h2 + (size_t)s * 16 + q);
        acc.x += v.x * wt; acc.y += v.y * wt; acc.z += v.z * wt; acc.w += v.w * wt;
    }
    float4 b = *(const float4*)(b2 + q);
    float4 v = make_float4(acc.x + b.x, acc.y + b.y, acc.z + b.z, acc.w + b.w);
    // group-of-4 max
    float m = fmaxf(fmaxf(v.x, v.y), fmaxf(v.z, v.w));
    m = fmaxf(m, __shfl_xor_sync(0xffffffffu, m, 1, 4));
    m = fmaxf(m, __shfl_xor_sync(0xffffffffu, m, 2, 4));
    float s4 = expf(v.x - m) + expf(v.y - m) + expf(v.z - m) + expf(v.w - m);
    s4 += __shfl_xor_sync(0xffffffffu, s4, 1, 4);
    s4 += __shfl_xor_sync(0xffffffffu, s4, 2, 4);
    float L = m + logf(s4);
    *(float4*)(out + (size_t)node * 16 + q) =
        make_float4(v.x - L, v.y - L, v.z - L, v.w - L);
}

// ---------------- launch ----------------
extern "C" void kernel_launch(void* const* d_in, const int* in_sizes, int n_in,
                              void* d_out, int out_size) {
    const float* x  = (const float*)d_in[0];
    const int*   ei = (const int*)d_in[1];
    const float* W1 = (const float*)d_in[2];
    const float* b1 = (const float*)d_in[3];
    const float* W2 = (const float*)d_in[4];
    const float* b2 = (const float*)d_in[5];
    float* out = (float*)d_out;

    int n = in_sizes[0] / 128;
    int E = in_sizes[1] / 2;

    k_init       <<<(n + 255) / 256, 256>>>(ei, n);
    k_convert_deg<<<(E + 255) / 256, 256>>>(ei, E);
    k_scan       <<<1, 1024>>>(n);
    k_place      <<<(E + 255) / 256, 256>>>(E);

    k_gemm1      <<<(n + 63) / 64, 128>>>(x, W1, n);
    k_gather1    <<<(n + 7) / 8, 256>>>(b1, n);
    k_gemm2      <<<(n + 255) / 256, 256>>>(W2, n);
    k_gather2    <<<(n * 4 + 255) / 256, 256>>>(out, b2, n);
}

// round 3
// speedup vs baseline: 1.0559x; 1.0559x over previous
#include <cuda_runtime.h>
#include <math.h>

#define NMAX 50000
#define EMAX 800000
#define SCAN_B 1024

// ---------------- scratch (static device memory) ----------------
__device__ float g_dinv[NMAX];
__device__ int   g_deg[NMAX];
__device__ int   g_off[NMAX + 1];
__device__ int   g_cur[NMAX];
__device__ int   g_bsum[64];
__device__ int2  g_csr[EMAX];                   // .x = src, .y = weight bits
__device__ float g_h1[(size_t)NMAX * 128];      // x @ W1
__device__ float g_h2[(size_t)NMAX * 16];       // relu(agg1+b1) @ W2
__device__ int   g_is64;                        // debug only

// ---------------- f32x2 packed math helpers ----------------
__device__ __forceinline__ unsigned long long pk2(float a, float b) {
    unsigned long long r;
    asm("mov.b64 %0, {%1, %2};" : "=l"(r) : "f"(a), "f"(b));
    return r;
}
__device__ __forceinline__ float2 up2(unsigned long long v) {
    float2 r;
    asm("mov.b64 {%0, %1}, %2;" : "=f"(r.x), "=f"(r.y) : "l"(v));
    return r;
}
__device__ __forceinline__ unsigned long long ffma2(unsigned long long a,
                                                    unsigned long long b,
                                                    unsigned long long c) {
    unsigned long long d;
    asm("fma.rn.f32x2 %0, %1, %2, %3;" : "=l"(d) : "l"(a), "l"(b), "l"(c));
    return d;
}

// ---------------- zero degree counters ----------------
__global__ void k_zero(int n) {
    int i = blockIdx.x * blockDim.x + threadIdx.x;
    if (i < n) g_deg[i] = 0;
}

// Per-block dtype detection: under int64 little-endian, words ei[2e+1] are the
// (always zero) high halves of src ids. Under int32 they are random node ids;
// a block of 256 of them being all-zero is statistically impossible.
// Reads stay within [0, 2E) -> in-bounds for both dtypes.
__device__ __forceinline__ int block_is64(const int* ei, int e, int E) {
    int v = (e < E) ? ei[2 * e + 1] : 0;
    int any = __syncthreads_or(v != 0);
    return any ? 0 : 1;
}

// ---------------- degree count (fused convert) ----------------
__global__ void k_deg(const int* __restrict__ ei, int E) {
    int e = blockIdx.x * blockDim.x + threadIdx.x;
    int is64 = block_is64(ei, e, E);
    if (e >= E) return;
    int d = is64 ? ei[2 * E + 2 * e] : ei[E + e];
    atomicAdd(&g_deg[d], 1);   // no return use -> RED
}

// ---------------- 3-phase exclusive scan of degrees (+ dinv) ----------------
__global__ __launch_bounds__(SCAN_B) void k_scan1(int n) {
    __shared__ int wsum[32];
    int tid = threadIdx.x, lane = tid & 31, wid = tid >> 5;
    int i = blockIdx.x * SCAN_B + tid;
    int deg = (i < n) ? g_deg[i] : 0;
    int v = deg;
#pragma unroll
    for (int o = 1; o < 32; o <<= 1) {
        int t = __shfl_up_sync(0xffffffffu, v, o);
        if (lane >= o) v += t;
    }
    if (lane == 31) wsum[wid] = v;
    __syncthreads();
    if (wid == 0) {
        int s = wsum[lane];
#pragma unroll
        for (int o = 1; o < 32; o <<= 1) {
            int t = __shfl_up_sync(0xffffffffu, s, o);
            if (lane >= o) s += t;
        }
        wsum[lane] = s;
    }
    __syncthreads();
    if (i < n) {
        g_off[i] = (wid ? wsum[wid - 1] : 0) + v - deg;   // block-local exclusive
        g_dinv[i] = rsqrtf((float)deg + 1.0f);
    }
    if (tid == 0) g_bsum[blockIdx.x] = wsum[31];          // block total
}

__global__ void k_scan2(int nb) {   // 1 warp, nb <= 64
    int lane = threadIdx.x;
    int v0 = (lane < nb) ? g_bsum[lane] : 0;
    int v1 = (lane + 32 < nb) ? g_bsum[lane + 32] : 0;
    int s0 = v0, s1 = v1;
#pragma unroll
    for (int o = 1; o < 32; o <<= 1) {
        int t0 = __shfl_up_sync(0xffffffffu, s0, o);
        int t1 = __shfl_up_sync(0xffffffffu, s1, o);
        if (lane >= o) { s0 += t0; s1 += t1; }
    }
    int tot0 = __shfl_sync(0xffffffffu, s0, 31);
    if (lane < nb)      g_bsum[lane]      = s0 - v0;
    if (lane + 32 < nb) g_bsum[lane + 32] = tot0 + s1 - v1;
}

__global__ __launch_bounds__(SCAN_B) void k_scan3(int n, int E) {
    int i = blockIdx.x * SCAN_B + threadIdx.x;
    if (i < n) {
        int o = g_off[i] + g_bsum[blockIdx.x];
        g_off[i] = o;
        g_cur[i] = o;
    }
    if (i == 0) g_off[n] = E;
}

// ---------------- place edges into CSR buckets (packed src+weight, one 8B store) ----------------
__global__ void k_place(const int* __restrict__ ei, int E) {
    int e = blockIdx.x * blockDim.x + threadIdx.x;
    int is64 = block_is64(ei, e, E);
    if (e >= E) return;
    int s, d;
    if (is64) { s = ei[2 * e]; d = ei[2 * E + 2 * e]; }
    else      { s = ei[e];     d = ei[E + e]; }
    int slot = atomicAdd(&g_cur[d], 1);
    int2 p;
    p.x = s;
    p.y = __float_as_int(g_dinv[s] * g_dinv[d]);
    g_csr[slot] = p;
}

// ---------------- GEMM1: h1 = x @ W1, 8x8 register tiles, packed f32x2 FFMA ----------------
__global__ __launch_bounds__(128) void k_gemm1(const float* __restrict__ x,
                                               const float* __restrict__ W,
                                               int n) {
    __shared__ float ws[32][128];
    __shared__ float xs[32][68];
    int tid = threadIdx.x;
    int row0 = blockIdx.x * 64;
    int tr = tid >> 4;
    int tc = tid & 15;
    unsigned long long acc[8][4];
#pragma unroll
    for (int r = 0; r < 8; ++r)
#pragma unroll
        for (int j = 0; j < 4; ++j) acc[r][j] = 0ull;

    for (int kc = 0; kc < 4; ++kc) {
        __syncthreads();
        for (int i = tid * 4; i < 32 * 128; i += 128 * 4)
            *(float4*)(&ws[0][0] + i) = *(const float4*)(W + kc * 32 * 128 + i);
        for (int i = tid; i < 64 * 32; i += 128) {
            int r = i >> 5, k = i & 31;
            int gr = row0 + r;
            xs[k][r] = (gr < n) ? x[(size_t)gr * 128 + kc * 32 + k] : 0.0f;
        }
        __syncthreads();
#pragma unroll 4
        for (int k = 0; k < 32; ++k) {
            float4 xa = *(const float4*)&xs[k][tr * 8];
            float4 xb = *(const float4*)&xs[k][tr * 8 + 4];
            float4 wa = *(const float4*)&ws[k][tc * 8];
            float4 wb = *(const float4*)&ws[k][tc * 8 + 4];
            unsigned long long wp[4] = { pk2(wa.x, wa.y), pk2(wa.z, wa.w),
                                         pk2(wb.x, wb.y), pk2(wb.z, wb.w) };
            unsigned long long xd[8] = { pk2(xa.x, xa.x), pk2(xa.y, xa.y),
                                         pk2(xa.z, xa.z), pk2(xa.w, xa.w),
                                         pk2(xb.x, xb.x), pk2(xb.y, xb.y),
                                         pk2(xb.z, xb.z), pk2(xb.w, xb.w) };
#pragma unroll
            for (int r = 0; r < 8; ++r)
#pragma unroll
                for (int j = 0; j < 4; ++j)
                    acc[r][j] = ffma2(xd[r], wp[j], acc[r][j]);
        }
    }
#pragma unroll
    for (int r = 0; r < 8; ++r) {
        int gr = row0 + tr * 8 + r;
        if (gr >= n) continue;
        float2 p0 = up2(acc[r][0]), p1 = up2(acc[r][1]);
        float2 p2 = up2(acc[r][2]), p3 = up2(acc[r][3]);
        float* dst = g_h1 + (size_t)gr * 128 + tc * 8;
        *(float4*)dst       = make_float4(p0.x, p0.y, p1.x, p1.y);
        *(float4*)(dst + 4) = make_float4(p2.x, p2.y, p3.x, p3.y);
    }
}

// ---------------- layer-1 gather (unroll 4) + relu + fused GEMM2 ----------------
// Warp per node; lane holds 4 row values. After aggregation the 128-float row is
// staged in smem; lanes 0..15 each compute one of the 16 outputs of h2.
__global__ __launch_bounds__(256) void k_gather1(const float* __restrict__ b1,
                                                 const float* __restrict__ W2,
                                                 int n) {
    __shared__ float w2s[128 * 16];   // row-major [k][c]
    __shared__ float rows[8][128];    // one 128-float row per warp
    int tid = threadIdx.x;
    for (int i = tid; i < 2048; i += 256) w2s[i] = W2[i];
    __syncthreads();

    int warp = tid >> 5, lane = tid & 31;
    int node = blockIdx.x * 8 + warp;
    if (node < n) {
        int c = lane << 2;
        float di = g_dinv[node];
        float w0 = di * di;
        float4 acc = *(const float4*)(g_h1 + (size_t)node * 128 + c);
        acc.x *= w0; acc.y *= w0; acc.z *= w0; acc.w *= w0;
        int e = g_off[node], e1 = g_off[node + 1];
        for (; e + 4 <= e1; e += 4) {
            int2 p0 = g_csr[e],     p1 = g_csr[e + 1];
            int2 p2 = g_csr[e + 2], p3 = g_csr[e + 3];
            float4 v0 = *(const float4*)(g_h1 + (size_t)p0.x * 128 + c);
            float4 v1 = *(const float4*)(g_h1 + (size_t)p1.x * 128 + c);
            float4 v2 = *(const float4*)(g_h1 + (size_t)p2.x * 128 + c);
            float4 v3 = *(const float4*)(g_h1 + (size_t)p3.x * 128 + c);
            float w0_ = __int_as_float(p0.y), w1_ = __int_as_float(p1.y);
            float w2_ = __int_as_float(p2.y), w3_ = __int_as_float(p3.y);
            acc.x += v0.x * w0_ + v1.x * w1_ + v2.x * w2_ + v3.x * w3_;
            acc.y += v0.y * w0_ + v1.y * w1_ + v2.y * w2_ + v3.y * w3_;
            acc.z += v0.z * w0_ + v1.z * w1_ + v2.z * w2_ + v3.z * w3_;
            acc.w += v0.w * w0_ + v1.w * w1_ + v2.w * w2_ + v3.w * w3_;
        }
        for (; e < e1; ++e) {
            int2 p = g_csr[e];
            float wt = __int_as_float(p.y);
            float4 v = *(const float4*)(g_h1 + (size_t)p.x * 128 + c);
            acc.x += v.x * wt; acc.y += v.y * wt; acc.z += v.z * wt; acc.w += v.w * wt;
        }
        float4 b = *(const float4*)(b1 + c);
        float4 o = make_float4(fmaxf(acc.x + b.x, 0.0f), fmaxf(acc.y + b.y, 0.0f),
                               fmaxf(acc.z + b.z, 0.0f), fmaxf(acc.w + b.w, 0.0f));
        *(float4*)&rows[warp][c] = o;
    }
    __syncwarp();
    if (node < n && lane < 16) {
        float s = 0.0f;
#pragma unroll 8
        for (int k = 0; k < 128; k += 4) {
            float4 r = *(const float4*)&rows[warp][k];
            s += r.x * w2s[(k + 0) * 16 + lane];
            s += r.y * w2s[(k + 1) * 16 + lane];
            s += r.z * w2s[(k + 2) * 16 + lane];
            s += r.w * w2s[(k + 3) * 16 + lane];
        }
        g_h2[(size_t)node * 16 + lane] = s;
    }
}

// ---------------- layer-2 gather (unroll 4) + b2 + log_softmax ----------------
__global__ __launch_bounds__(256) void k_gather2(float* __restrict__ out,
                                                 const float* __restrict__ b2, int n) {
    int idx = blockIdx.x * blockDim.x + threadIdx.x;
    int node = idx >> 2;
    if (node >= n) return;
    int q = (idx & 3) << 2;
    float di = g_dinv[node];
    float w0 = di * di;
    float4 acc = *(const float4*)(g_h2 + (size_t)node * 16 + q);
    acc.x *= w0; acc.y *= w0; acc.z *= w0; acc.w *= w0;
    int e = g_off[node], e1 = g_off[node + 1];
    for (; e + 4 <= e1; e += 4) {
        int2 p0 = g_csr[e],     p1 = g_csr[e + 1];
        int2 p2 = g_csr[e + 2], p3 = g_csr[e + 3];
        float4 v0 = *(const float4*)(g_h2 + (size_t)p0.x * 16 + q);
        float4 v1 = *(const float4*)(g_h2 + (size_t)p1.x * 16 + q);
        float4 v2 = *(const float4*)(g_h2 + (size_t)p2.x * 16 + q);
        float4 v3 = *(const float4*)(g_h2 + (size_t)p3.x * 16 + q);
        float w0_ = __int_as_float(p0.y), w1_ = __int_as_float(p1.y);
        float w2_ = __int_as_float(p2.y), w3_ = __int_as_float(p3.y);
        acc.x += v0.x * w0_ + v1.x * w1_ + v2.x * w2_ + v3.x * w3_;
        acc.y += v0.y * w0_ + v1.y * w1_ + v2.y * w2_ + v3.y * w3_;
        acc.z += v0.z * w0_ + v1.z * w1_ + v2.z * w2_ + v3.z * w3_;
        acc.w += v0.w * w0_ + v1.w * w1_ + v2.w * w2_ + v3.w * w3_;
    }
    for (; e < e1; ++e) {
        int2 p = g_csr[e];
        float wt = __int_as_float(p.y);
        float4 v = *(const float4*)(g_h2 + (size_t)p.x * 16 + q);
        acc.x += v.x * wt; acc.y += v.y * wt; acc.z += v.z * wt; acc.w += v.w * wt;
    }
    float4 b = *(const float4*)(b2 + q);
    float4 v = make_float4(acc.x + b.x, acc.y + b.y, acc.z + b.z, acc.w + b.w);
    float m = fmaxf(fmaxf(v.x, v.y), fmaxf(v.z, v.w));
    m = fmaxf(m, __shfl_xor_sync(0xffffffffu, m, 1, 4));
    m = fmaxf(m, __shfl_xor_sync(0xffffffffu, m, 2, 4));
    float s4 = expf(v.x - m) + expf(v.y - m) + expf(v.z - m) + expf(v.w - m);
    s4 += __shfl_xor_sync(0xffffffffu, s4, 1, 4);
    s4 += __shfl_xor_sync(0xffffffffu, s4, 2, 4);
    float L = m + logf(s4);
    *(float4*)(out + (size_t)node * 16 + q) =
        make_float4(v.x - L, v.y - L, v.z - L, v.w - L);
}

// ---------------- launch ----------------
extern "C" void kernel_launch(void* const* d_in, const int* in_sizes, int n_in,
                              void* d_out, int out_size) {
    const float* x  = (const float*)d_in[0];
    const int*   ei = (const int*)d_in[1];
    const float* W1 = (const float*)d_in[2];
    const float* b1 = (const float*)d_in[3];
    const float* W2 = (const float*)d_in[4];
    const float* b2 = (const float*)d_in[5];
    float* out = (float*)d_out;

    int n = in_sizes[0] / 128;
    int E = in_sizes[1] / 2;
    int nsb = (n + SCAN_B - 1) / SCAN_B;

    k_zero  <<<(n + 255) / 256, 256>>>(n);
    k_deg   <<<(E + 255) / 256, 256>>>(ei, E);
    k_scan1 <<<nsb, SCAN_B>>>(n);
    k_scan2 <<<1, 32>>>(nsb);
    k_scan3 <<<nsb, SCAN_B>>>(n, E);
    k_place <<<(E + 255) / 256, 256>>>(ei, E);

    k_gemm1  <<<(n + 63) / 64, 128>>>(x, W1, n);
    k_gather1<<<(n + 7) / 8, 256>>>(b1, W2, n);
    k_gather2<<<(n * 4 + 255) / 256, 256>>>(out, b2, n);
}

// round 4
// speedup vs baseline: 1.6919x; 1.6023x over previous
#include <cuda_runtime.h>
#include <math.h>

#define NMAX 50000
#define EMAX 800000
#define SCAN_B 1024

// ---------------- scratch (static device memory) ----------------
__device__ float g_dinv[NMAX];
__device__ int   g_deg[NMAX];
__device__ int   g_off[NMAX + 1];
__device__ int   g_cur[NMAX];
__device__ volatile int g_pref[64];             // chained-scan prefixes (-1 = not ready)
__device__ int2  g_csr[EMAX];                   // .x = src, .y = weight bits
__device__ float g_h1[(size_t)NMAX * 128];      // x @ W1
__device__ float g_h2[(size_t)NMAX * 16];       // relu(agg1+b1) @ W2

// ---------------- f32x2 packed math helpers ----------------
__device__ __forceinline__ unsigned long long pk2(float a, float b) {
    unsigned long long r;
    asm("mov.b64 %0, {%1, %2};" : "=l"(r) : "f"(a), "f"(b));
    return r;
}
__device__ __forceinline__ float2 up2(unsigned long long v) {
    float2 r;
    asm("mov.b64 {%0, %1}, %2;" : "=f"(r.x), "=f"(r.y) : "l"(v));
    return r;
}
__device__ __forceinline__ unsigned long long ffma2(unsigned long long a,
                                                    unsigned long long b,
                                                    unsigned long long c) {
    unsigned long long d;
    asm("fma.rn.f32x2 %0, %1, %2, %3;" : "=l"(d) : "l"(a), "l"(b), "l"(c));
    return d;
}

// ---------------- zero degree counters + scan sentinels ----------------
__global__ void k_zero(int n, int nb) {
    int i = blockIdx.x * blockDim.x + threadIdx.x;
    if (i < n) g_deg[i] = 0;
    if (i < nb) g_pref[i] = -1;
}

// Per-block dtype detection: under int64 little-endian, words ei[2e+1] are the
// (always zero) high halves of src ids; under int32 they are random node ids.
__device__ __forceinline__ int block_is64(const int* ei, int e, int E) {
    int v = (e < E) ? ei[2 * e + 1] : 0;
    int any = __syncthreads_or(v != 0);
    return any ? 0 : 1;
}

// ---------------- degree count (fused convert) ----------------
__global__ void k_deg(const int* __restrict__ ei, int E) {
    int e = blockIdx.x * blockDim.x + threadIdx.x;
    int is64 = block_is64(ei, e, E);
    if (e >= E) return;
    int d = is64 ? ei[2 * E + 2 * e] : ei[E + e];
    atomicAdd(&g_deg[d], 1);   // no return use -> RED
}

// ---------------- single-kernel chained exclusive scan (+ dinv, + g_cur) ----------------
__global__ __launch_bounds__(SCAN_B) void k_scan(int n, int E, int nb) {
    __shared__ int wsum[32];
    __shared__ int prefix_s;
    int tid = threadIdx.x, lane = tid & 31, wid = tid >> 5;
    int b = blockIdx.x;
    int i = b * SCAN_B + tid;
    int deg = (i < n) ? g_deg[i] : 0;
    int v = deg;
#pragma unroll
    for (int o = 1; o < 32; o <<= 1) {
        int t = __shfl_up_sync(0xffffffffu, v, o);
        if (lane >= o) v += t;
    }
    if (lane == 31) wsum[wid] = v;
    __syncthreads();
    if (wid == 0) {
        int s = wsum[lane];
#pragma unroll
        for (int o = 1; o < 32; o <<= 1) {
            int t = __shfl_up_sync(0xffffffffu, s, o);
            if (lane >= o) s += t;
        }
        wsum[lane] = s;
    }
    __syncthreads();
    int total = wsum[31];
    if (tid == 0) {
        int prev = 0;
        if (b > 0) {
            while ((prev = g_pref[b - 1]) == -1) { }
        }
        __threadfence();
        g_pref[b] = prev + total;     // publish inclusive prefix (single 4B store)
        prefix_s = prev;
        if (b == nb - 1) g_off[n] = E;
    }
    __syncthreads();
    if (i < n) {
        int o = prefix_s + (wid ? wsum[wid - 1] : 0) + v - deg;
        g_off[i] = o;
        g_cur[i] = o;
        g_dinv[i] = rsqrtf((float)deg + 1.0f);
    }
}

// ---------------- place edges into CSR buckets (packed src+weight, one 8B store) ----------------
__global__ void k_place(const int* __restrict__ ei, int E) {
    int e = blockIdx.x * blockDim.x + threadIdx.x;
    int is64 = block_is64(ei, e, E);
    if (e >= E) return;
    int s, d;
    if (is64) { s = ei[2 * e]; d = ei[2 * E + 2 * e]; }
    else      { s = ei[e];     d = ei[E + e]; }
    int slot = atomicAdd(&g_cur[d], 1);
    int2 p;
    p.x = s;
    p.y = __float_as_int(g_dinv[s] * g_dinv[d]);
    g_csr[slot] = p;
}

// ---------------- GEMM1: h1 = x @ W1, 8x8 register tiles, packed f32x2 FFMA ----------------
__global__ __launch_bounds__(128) void k_gemm1(const float* __restrict__ x,
                                               const float* __restrict__ W,
                                               int n) {
    __shared__ float ws[32][128];
    __shared__ float xs[32][68];
    int tid = threadIdx.x;
    int row0 = blockIdx.x * 64;
    int tr = tid >> 4;
    int tc = tid & 15;
    unsigned long long acc[8][4];
#pragma unroll
    for (int r = 0; r < 8; ++r)
#pragma unroll
        for (int j = 0; j < 4; ++j) acc[r][j] = 0ull;

    for (int kc = 0; kc < 4; ++kc) {
        __syncthreads();
        for (int i = tid * 4; i < 32 * 128; i += 128 * 4)
            *(float4*)(&ws[0][0] + i) = *(const float4*)(W + kc * 32 * 128 + i);
        for (int i = tid; i < 64 * 32; i += 128) {
            int r = i >> 5, k = i & 31;
            int gr = row0 + r;
            xs[k][r] = (gr < n) ? x[(size_t)gr * 128 + kc * 32 + k] : 0.0f;
        }
        __syncthreads();
#pragma unroll 4
        for (int k = 0; k < 32; ++k) {
            float4 xa = *(const float4*)&xs[k][tr * 8];
            float4 xb = *(const float4*)&xs[k][tr * 8 + 4];
            float4 wa = *(const float4*)&ws[k][tc * 8];
            float4 wb = *(const float4*)&ws[k][tc * 8 + 4];
            unsigned long long wp[4] = { pk2(wa.x, wa.y), pk2(wa.z, wa.w),
                                         pk2(wb.x, wb.y), pk2(wb.z, wb.w) };
            unsigned long long xd[8] = { pk2(xa.x, xa.x), pk2(xa.y, xa.y),
                                         pk2(xa.z, xa.z), pk2(xa.w, xa.w),
                                         pk2(xb.x, xb.x), pk2(xb.y, xb.y),
                                         pk2(xb.z, xb.z), pk2(xb.w, xb.w) };
#pragma unroll
            for (int r = 0; r < 8; ++r)
#pragma unroll
                for (int j = 0; j < 4; ++j)
                    acc[r][j] = ffma2(xd[r], wp[j], acc[r][j]);
        }
    }
#pragma unroll
    for (int r = 0; r < 8; ++r) {
        int gr = row0 + tr * 8 + r;
        if (gr >= n) continue;
        float2 p0 = up2(acc[r][0]), p1 = up2(acc[r][1]);
        float2 p2 = up2(acc[r][2]), p3 = up2(acc[r][3]);
        float* dst = g_h1 + (size_t)gr * 128 + tc * 8;
        *(float4*)dst       = make_float4(p0.x, p0.y, p1.x, p1.y);
        *(float4*)(dst + 4) = make_float4(p2.x, p2.y, p3.x, p3.y);
    }
}

// ---------------- layer-1 gather (unroll 4) + relu + fused GEMM2 ----------------
__global__ __launch_bounds__(256) void k_gather1(const float* __restrict__ b1,
                                                 const float* __restrict__ W2,
                                                 int n) {
    __shared__ float w2s[128 * 16];   // row-major [k][c]
    __shared__ float rows[8][128];
    int tid = threadIdx.x;
    for (int i = tid; i < 2048; i += 256) w2s[i] = W2[i];
    __syncthreads();

    int warp = tid >> 5, lane = tid & 31;
    int node = blockIdx.x * 8 + warp;
    if (node < n) {
        int c = lane << 2;
        float di = g_dinv[node];
        float w0 = di * di;
        float4 acc = *(const float4*)(g_h1 + (size_t)node * 128 + c);
        acc.x *= w0; acc.y *= w0; acc.z *= w0; acc.w *= w0;
        int e = g_off[node], e1 = g_off[node + 1];
        for (; e + 4 <= e1; e += 4) {
            int2 p0 = g_csr[e],     p1 = g_csr[e + 1];
            int2 p2 = g_csr[e + 2], p3 = g_csr[e + 3];
            float4 v0 = *(const float4*)(g_h1 + (size_t)p0.x * 128 + c);
            float4 v1 = *(const float4*)(g_h1 + (size_t)p1.x * 128 + c);
            float4 v2 = *(const float4*)(g_h1 + (size_t)p2.x * 128 + c);
            float4 v3 = *(const float4*)(g_h1 + (size_t)p3.x * 128 + c);
            float w0_ = __int_as_float(p0.y), w1_ = __int_as_float(p1.y);
            float w2_ = __int_as_float(p2.y), w3_ = __int_as_float(p3.y);
            acc.x += v0.x * w0_ + v1.x * w1_ + v2.x * w2_ + v3.x * w3_;
            acc.y += v0.y * w0_ + v1.y * w1_ + v2.y * w2_ + v3.y * w3_;
            acc.z += v0.z * w0_ + v1.z * w1_ + v2.z * w2_ + v3.z * w3_;
            acc.w += v0.w * w0_ + v1.w * w1_ + v2.w * w2_ + v3.w * w3_;
        }
        for (; e < e1; ++e) {
            int2 p = g_csr[e];
            float wt = __int_as_float(p.y);
            float4 v = *(const float4*)(g_h1 + (size_t)p.x * 128 + c);
            acc.x += v.x * wt; acc.y += v.y * wt; acc.z += v.z * wt; acc.w += v.w * wt;
        }
        float4 b = *(const float4*)(b1 + c);
        float4 o = make_float4(fmaxf(acc.x + b.x, 0.0f), fmaxf(acc.y + b.y, 0.0f),
                               fmaxf(acc.z + b.z, 0.0f), fmaxf(acc.w + b.w, 0.0f));
        *(float4*)&rows[warp][c] = o;
    }
    __syncwarp();
    if (node < n && lane < 16) {
        float s = 0.0f;
#pragma unroll 8
        for (int k = 0; k < 128; k += 4) {
            float4 r = *(const float4*)&rows[warp][k];
            s += r.x * w2s[(k + 0) * 16 + lane];
            s += r.y * w2s[(k + 1) * 16 + lane];
            s += r.z * w2s[(k + 2) * 16 + lane];
            s += r.w * w2s[(k + 3) * 16 + lane];
        }
        g_h2[(size_t)node * 16 + lane] = s;
    }
}

// ---------------- layer-2 gather (unroll 4) + b2 + log_softmax ----------------
__global__ __launch_bounds__(256) void k_gather2(float* __restrict__ out,
                                                 const float* __restrict__ b2, int n) {
    int idx = blockIdx.x * blockDim.x + threadIdx.x;
    int node = idx >> 2;
    if (node >= n) return;
    int q = (idx & 3) << 2;
    float di = g_dinv[node];
    float w0 = di * di;
    float4 acc = *(const float4*)(g_h2 + (size_t)node * 16 + q);
    acc.x *= w0; acc.y *= w0; acc.z *= w0; acc.w *= w0;
    int e = g_off[node], e1 = g_off[node + 1];
    for (; e + 4 <= e1; e += 4) {
        int2 p0 = g_csr[e],     p1 = g_csr[e + 1];
        int2 p2 = g_csr[e + 2], p3 = g_csr[e + 3];
        float4 v0 = *(const float4*)(g_h2 + (size_t)p0.x * 16 + q);
        float4 v1 = *(const float4*)(g_h2 + (size_t)p1.x * 16 + q);
        float4 v2 = *(const float4*)(g_h2 + (size_t)p2.x * 16 + q);
        float4 v3 = *(const float4*)(g_h2 + (size_t)p3.x * 16 + q);
        float w0_ = __int_as_float(p0.y), w1_ = __int_as_float(p1.y);
        float w2_ = __int_as_float(p2.y), w3_ = __int_as_float(p3.y);
        acc.x += v0.x * w0_ + v1.x * w1_ + v2.x * w2_ + v3.x * w3_;
        acc.y += v0.y * w0_ + v1.y * w1_ + v2.y * w2_ + v3.y * w3_;
        acc.z += v0.z * w0_ + v1.z * w1_ + v2.z * w2_ + v3.z * w3_;
        acc.w += v0.w * w0_ + v1.w * w1_ + v2.w * w2_ + v3.w * w3_;
    }
    for (; e < e1; ++e) {
        int2 p = g_csr[e];
        float wt = __int_as_float(p.y);
        float4 v = *(const float4*)(g_h2 + (size_t)p.x * 16 + q);
        acc.x += v.x * wt; acc.y += v.y * wt; acc.z += v.z * wt; acc.w += v.w * wt;
    }
    float4 b = *(const float4*)(b2 + q);
    float4 v = make_float4(acc.x + b.x, acc.y + b.y, acc.z + b.z, acc.w + b.w);
    float m = fmaxf(fmaxf(v.x, v.y), fmaxf(v.z, v.w));
    m = fmaxf(m, __shfl_xor_sync(0xffffffffu, m, 1, 4));
    m = fmaxf(m, __shfl_xor_sync(0xffffffffu, m, 2, 4));
    float s4 = expf(v.x - m) + expf(v.y - m) + expf(v.z - m) + expf(v.w - m);
    s4 += __shfl_xor_sync(0xffffffffu, s4, 1, 4);
    s4 += __shfl_xor_sync(0xffffffffu, s4, 2, 4);
    float L = m + logf(s4);
    *(float4*)(out + (size_t)node * 16 + q) =
        make_float4(v.x - L, v.y - L, v.z - L, v.w - L);
}

// ---------------- launch: fork/join, build-chain || gemm1 ----------------
extern "C" void kernel_launch(void* const* d_in, const int* in_sizes, int n_in,
                              void* d_out, int out_size) {
    const float* x  = (const float*)d_in[0];
    const int*   ei = (const int*)d_in[1];
    const float* W1 = (const float*)d_in[2];
    const float* b1 = (const float*)d_in[3];
    const float* W2 = (const float*)d_in[4];
    const float* b2 = (const float*)d_in[5];
    float* out = (float*)d_out;

    int n = in_sizes[0] / 128;
    int E = in_sizes[1] / 2;
    int nsb = (n + SCAN_B - 1) / SCAN_B;

    static cudaStream_t s1 = nullptr, s2 = nullptr;
    static cudaEvent_t ev0 = nullptr, ev1 = nullptr, ev2 = nullptr;
    if (!s1) {
        cudaStreamCreateWithFlags(&s1, cudaStreamNonBlocking);
        cudaStreamCreateWithFlags(&s2, cudaStreamNonBlocking);
        cudaEventCreateWithFlags(&ev0, cudaEventDisableTiming);
        cudaEventCreateWithFlags(&ev1, cudaEventDisableTiming);
        cudaEventCreateWithFlags(&ev2, cudaEventDisableTiming);
    }

    cudaEventRecord(ev0, 0);          // fork from the origin (legacy) stream
    cudaStreamWaitEvent(s1, ev0, 0);
    cudaStreamWaitEvent(s2, ev0, 0);

    // branch 1: CSR build
    k_zero <<<(n + 255) / 256, 256, 0, s1>>>(n, nsb);
    k_deg  <<<(E + 255) / 256, 256, 0, s1>>>(ei, E);
    k_scan <<<nsb, SCAN_B, 0, s1>>>(n, E, nsb);
    k_place<<<(E + 255) / 256, 256, 0, s1>>>(ei, E);
    cudaEventRecord(ev1, s1);

    // branch 2: dense GEMM1
    k_gemm1<<<(n + 63) / 64, 128, 0, s2>>>(x, W1, n);
    cudaEventRecord(ev2, s2);

    // join on origin stream
    cudaStreamWaitEvent(0, ev1, 0);
    cudaStreamWaitEvent(0, ev2, 0);

    k_gather1<<<(n + 7) / 8, 256>>>(b1, W2, n);
    k_gather2<<<(n * 4 + 255) / 256, 256>>>(out, b2, n);
}

// round 5
// speedup vs baseline: 1.7171x; 1.0149x over previous
#include <cuda_runtime.h>
#include <cuda_fp16.h>
#include <math.h>

#define NMAX 50000
#define EMAX 800000
#define SCAN_B 1024

// ---------------- scratch (static device memory) ----------------
__device__ float  g_dinv[NMAX];
__device__ int    g_deg[NMAX];
__device__ int    g_off[NMAX + 1];
__device__ int    g_cur[NMAX];
__device__ volatile int g_pref[64];              // chained-scan prefixes (-1 = not ready)
__device__ int2   g_csr[EMAX];                   // .x = src, .y = weight bits
__device__ __half g_h1[(size_t)NMAX * 128];      // x @ W1  (fp16 storage, fp32 accum)
__device__ float  g_h2[(size_t)NMAX * 16];       // relu(agg1+b1) @ W2

// ---------------- f32x2 packed math helpers ----------------
__device__ __forceinline__ unsigned long long pk2(float a, float b) {
    unsigned long long r;
    asm("mov.b64 %0, {%1, %2};" : "=l"(r) : "f"(a), "f"(b));
    return r;
}
__device__ __forceinline__ float2 up2(unsigned long long v) {
    float2 r;
    asm("mov.b64 {%0, %1}, %2;" : "=f"(r.x), "=f"(r.y) : "l"(v));
    return r;
}
__device__ __forceinline__ unsigned long long ffma2(unsigned long long a,
                                                    unsigned long long b,
                                                    unsigned long long c) {
    unsigned long long d;
    asm("fma.rn.f32x2 %0, %1, %2, %3;" : "=l"(d) : "l"(a), "l"(b), "l"(c));
    return d;
}

// ---------------- zero degree counters + scan sentinels ----------------
__global__ void k_zero(int n, int nb) {
    int i = blockIdx.x * blockDim.x + threadIdx.x;
    if (i < n) g_deg[i] = 0;
    if (i < nb) g_pref[i] = -1;
}

// Per-block dtype detection: under int64 little-endian, words ei[2e+1] are the
// (always zero) high halves of src ids; under int32 they are random node ids.
__device__ __forceinline__ int block_is64(const int* ei, int e, int E) {
    int v = (e < E) ? ei[2 * e + 1] : 0;
    int any = __syncthreads_or(v != 0);
    return any ? 0 : 1;
}

// ---------------- degree count (fused convert) ----------------
__global__ void k_deg(const int* __restrict__ ei, int E) {
    int e = blockIdx.x * blockDim.x + threadIdx.x;
    int is64 = block_is64(ei, e, E);
    if (e >= E) return;
    int d = is64 ? ei[2 * E + 2 * e] : ei[E + e];
    atomicAdd(&g_deg[d], 1);   // no return use -> RED
}

// ---------------- single-kernel chained exclusive scan (+ dinv, + g_cur) ----------------
__global__ __launch_bounds__(SCAN_B) void k_scan(int n, int E, int nb) {
    __shared__ int wsum[32];
    __shared__ int prefix_s;
    int tid = threadIdx.x, lane = tid & 31, wid = tid >> 5;
    int b = blockIdx.x;
    int i = b * SCAN_B + tid;
    int deg = (i < n) ? g_deg[i] : 0;
    int v = deg;
#pragma unroll
    for (int o = 1; o < 32; o <<= 1) {
        int t = __shfl_up_sync(0xffffffffu, v, o);
        if (lane >= o) v += t;
    }
    if (lane == 31) wsum[wid] = v;
    __syncthreads();
    if (wid == 0) {
        int s = wsum[lane];
#pragma unroll
        for (int o = 1; o < 32; o <<= 1) {
            int t = __shfl_up_sync(0xffffffffu, s, o);
            if (lane >= o) s += t;
        }
        wsum[lane] = s;
    }
    __syncthreads();
    int total = wsum[31];
    if (tid == 0) {
        int prev = 0;
        if (b > 0) {
            while ((prev = g_pref[b - 1]) == -1) { }
        }
        __threadfence();
        g_pref[b] = prev + total;
        prefix_s = prev;
        if (b == nb - 1) g_off[n] = E;
    }
    __syncthreads();
    if (i < n) {
        int o = prefix_s + (wid ? wsum[wid - 1] : 0) + v - deg;
        g_off[i] = o;
        g_cur[i] = o;
        g_dinv[i] = rsqrtf((float)deg + 1.0f);
    }
}

// ---------------- place edges into CSR buckets (packed src+weight, one 8B store) ----------------
__global__ void k_place(const int* __restrict__ ei, int E) {
    int e = blockIdx.x * blockDim.x + threadIdx.x;
    int is64 = block_is64(ei, e, E);
    if (e >= E) return;
    int s, d;
    if (is64) { s = ei[2 * e]; d = ei[2 * E + 2 * e]; }
    else      { s = ei[e];     d = ei[E + e]; }
    int slot = atomicAdd(&g_cur[d], 1);
    int2 p;
    p.x = s;
    p.y = __float_as_int(g_dinv[s] * g_dinv[d]);
    g_csr[slot] = p;
}

// ---------------- GEMM1: h1 = x @ W1 -> fp16 store ----------------
__global__ __launch_bounds__(128) void k_gemm1(const float* __restrict__ x,
                                               const float* __restrict__ W,
                                               int n) {
    __shared__ float ws[32][128];
    __shared__ float xs[32][68];
    int tid = threadIdx.x;
    int row0 = blockIdx.x * 64;
    int tr = tid >> 4;
    int tc = tid & 15;
    unsigned long long acc[8][4];
#pragma unroll
    for (int r = 0; r < 8; ++r)
#pragma unroll
        for (int j = 0; j < 4; ++j) acc[r][j] = 0ull;

    for (int kc = 0; kc < 4; ++kc) {
        __syncthreads();
        for (int i = tid * 4; i < 32 * 128; i += 128 * 4)
            *(float4*)(&ws[0][0] + i) = *(const float4*)(W + kc * 32 * 128 + i);
        for (int i = tid; i < 64 * 32; i += 128) {
            int r = i >> 5, k = i & 31;
            int gr = row0 + r;
            xs[k][r] = (gr < n) ? x[(size_t)gr * 128 + kc * 32 + k] : 0.0f;
        }
        __syncthreads();
#pragma unroll 4
        for (int k = 0; k < 32; ++k) {
            float4 xa = *(const float4*)&xs[k][tr * 8];
            float4 xb = *(const float4*)&xs[k][tr * 8 + 4];
            float4 wa = *(const float4*)&ws[k][tc * 8];
            float4 wb = *(const float4*)&ws[k][tc * 8 + 4];
            unsigned long long wp[4] = { pk2(wa.x, wa.y), pk2(wa.z, wa.w),
                                         pk2(wb.x, wb.y), pk2(wb.z, wb.w) };
            unsigned long long xd[8] = { pk2(xa.x, xa.x), pk2(xa.y, xa.y),
                                         pk2(xa.z, xa.z), pk2(xa.w, xa.w),
                                         pk2(xb.x, xb.x), pk2(xb.y, xb.y),
                                         pk2(xb.z, xb.z), pk2(xb.w, xb.w) };
#pragma unroll
            for (int r = 0; r < 8; ++r)
#pragma unroll
                for (int j = 0; j < 4; ++j)
                    acc[r][j] = ffma2(xd[r], wp[j], acc[r][j]);
        }
    }
#pragma unroll
    for (int r = 0; r < 8; ++r) {
        int gr = row0 + tr * 8 + r;
        if (gr >= n) continue;
        float2 p0 = up2(acc[r][0]), p1 = up2(acc[r][1]);
        float2 p2 = up2(acc[r][2]), p3 = up2(acc[r][3]);
        __half2 h[4] = { __float22half2_rn(p0), __float22half2_rn(p1),
                         __float22half2_rn(p2), __float22half2_rn(p3) };
        // 8 halves = 16 bytes, aligned (tc*8 halves = tc*16 bytes)
        *(uint4*)(g_h1 + (size_t)gr * 128 + tc * 8) = *(const uint4*)h;
    }
}

// ---------------- layer-1 gather (fp16 rows, unroll 4) + relu + fused GEMM2 ----------------
__device__ __forceinline__ float4 ld_h4(const __half* p) {
    uint2 u = *(const uint2*)p;
    float2 a = __half22float2(*(const __half2*)&u.x);
    float2 b = __half22float2(*(const __half2*)&u.y);
    return make_float4(a.x, a.y, b.x, b.y);
}

__global__ __launch_bounds__(256) void k_gather1(const float* __restrict__ b1,
                                                 const float* __restrict__ W2,
                                                 int n) {
    __shared__ float w2s[128 * 16];   // row-major [k][c]
    __shared__ float rows[8][128];
    int tid = threadIdx.x;
    for (int i = tid; i < 2048; i += 256) w2s[i] = W2[i];
    __syncthreads();

    int warp = tid >> 5, lane = tid & 31;
    int node = blockIdx.x * 8 + warp;
    if (node < n) {
        int c = lane << 2;
        float di = g_dinv[node];
        float w0 = di * di;
        float4 acc = ld_h4(g_h1 + (size_t)node * 128 + c);
        acc.x *= w0; acc.y *= w0; acc.z *= w0; acc.w *= w0;
        int e = g_off[node], e1 = g_off[node + 1];
        for (; e + 4 <= e1; e += 4) {
            int2 p0 = g_csr[e],     p1 = g_csr[e + 1];
            int2 p2 = g_csr[e + 2], p3 = g_csr[e + 3];
            float4 v0 = ld_h4(g_h1 + (size_t)p0.x * 128 + c);
            float4 v1 = ld_h4(g_h1 + (size_t)p1.x * 128 + c);
            float4 v2 = ld_h4(g_h1 + (size_t)p2.x * 128 + c);
            float4 v3 = ld_h4(g_h1 + (size_t)p3.x * 128 + c);
            float w0_ = __int_as_float(p0.y), w1_ = __int_as_float(p1.y);
            float w2_ = __int_as_float(p2.y), w3_ = __int_as_float(p3.y);
            acc.x += v0.x * w0_ + v1.x * w1_ + v2.x * w2_ + v3.x * w3_;
            acc.y += v0.y * w0_ + v1.y * w1_ + v2.y * w2_ + v3.y * w3_;
            acc.z += v0.z * w0_ + v1.z * w1_ + v2.z * w2_ + v3.z * w3_;
            acc.w += v0.w * w0_ + v1.w * w1_ + v2.w * w2_ + v3.w * w3_;
        }
        for (; e < e1; ++e) {
            int2 p = g_csr[e];
            float wt = __int_as_float(p.y);
            float4 v = ld_h4(g_h1 + (size_t)p.x * 128 + c);
            acc.x += v.x * wt; acc.y += v.y * wt; acc.z += v.z * wt; acc.w += v.w * wt;
        }
        float4 b = *(const float4*)(b1 + c);
        float4 o = make_float4(fmaxf(acc.x + b.x, 0.0f), fmaxf(acc.y + b.y, 0.0f),
                               fmaxf(acc.z + b.z, 0.0f), fmaxf(acc.w + b.w, 0.0f));
        *(float4*)&rows[warp][c] = o;
    }
    __syncwarp();
    if (node < n && lane < 16) {
        float s = 0.0f;
#pragma unroll 8
        for (int k = 0; k < 128; k += 4) {
            float4 r = *(const float4*)&rows[warp][k];
            s += r.x * w2s[(k + 0) * 16 + lane];
            s += r.y * w2s[(k + 1) * 16 + lane];
            s += r.z * w2s[(k + 2) * 16 + lane];
            s += r.w * w2s[(k + 3) * 16 + lane];
        }
        g_h2[(size_t)node * 16 + lane] = s;
    }
}

// ---------------- layer-2 gather (unroll 4) + b2 + log_softmax ----------------
__global__ __launch_bounds__(256) void k_gather2(float* __restrict__ out,
                                                 const float* __restrict__ b2, int n) {
    int idx = blockIdx.x * blockDim.x + threadIdx.x;
    int node = idx >> 2;
    if (node >= n) return;
    int q = (idx & 3) << 2;
    float di = g_dinv[node];
    float w0 = di * di;
    float4 acc = *(const float4*)(g_h2 + (size_t)node * 16 + q);
    acc.x *= w0; acc.y *= w0; acc.z *= w0; acc.w *= w0;
    int e = g_off[node], e1 = g_off[node + 1];
    for (; e + 4 <= e1; e += 4) {
        int2 p0 = g_csr[e],     p1 = g_csr[e + 1];
        int2 p2 = g_csr[e + 2], p3 = g_csr[e + 3];
        float4 v0 = *(const float4*)(g_h2 + (size_t)p0.x * 16 + q);
        float4 v1 = *(const float4*)(g_h2 + (size_t)p1.x * 16 + q);
        float4 v2 = *(const float4*)(g_h2 + (size_t)p2.x * 16 + q);
        float4 v3 = *(const float4*)(g_h2 + (size_t)p3.x * 16 + q);
        float w0_ = __int_as_float(p0.y), w1_ = __int_as_float(p1.y);
        float w2_ = __int_as_float(p2.y), w3_ = __int_as_float(p3.y);
        acc.x += v0.x * w0_ + v1.x * w1_ + v2.x * w2_ + v3.x * w3_;
        acc.y += v0.y * w0_ + v1.y * w1_ + v2.y * w2_ + v3.y * w3_;
        acc.z += v0.z * w0_ + v1.z * w1_ + v2.z * w2_ + v3.z * w3_;
        acc.w += v0.w * w0_ + v1.w * w1_ + v2.w * w2_ + v3.w * w3_;
    }
    for (; e < e1; ++e) {
        int2 p = g_csr[e];
        float wt = __int_as_float(p.y);
        float4 v = *(const float4*)(g_h2 + (size_t)p.x * 16 + q);
        acc.x += v.x * wt; acc.y += v.y * wt; acc.z += v.z * wt; acc.w += v.w * wt;
    }
    float4 b = *(const float4*)(b2 + q);
    float4 v = make_float4(acc.x + b.x, acc.y + b.y, acc.z + b.z, acc.w + b.w);
    float m = fmaxf(fmaxf(v.x, v.y), fmaxf(v.z, v.w));
    m = fmaxf(m, __shfl_xor_sync(0xffffffffu, m, 1, 4));
    m = fmaxf(m, __shfl_xor_sync(0xffffffffu, m, 2, 4));
    float s4 = expf(v.x - m) + expf(v.y - m) + expf(v.z - m) + expf(v.w - m);
    s4 += __shfl_xor_sync(0xffffffffu, s4, 1, 4);
    s4 += __shfl_xor_sync(0xffffffffu, s4, 2, 4);
    float L = m + logf(s4);
    *(float4*)(out + (size_t)node * 16 + q) =
        make_float4(v.x - L, v.y - L, v.z - L, v.w - L);
}

// ---------------- launch: fork/join, build-chain || gemm1 ----------------
extern "C" void kernel_launch(void* const* d_in, const int* in_sizes, int n_in,
                              void* d_out, int out_size) {
    const float* x  = (const float*)d_in[0];
    const int*   ei = (const int*)d_in[1];
    const float* W1 = (const float*)d_in[2];
    const float* b1 = (const float*)d_in[3];
    const float* W2 = (const float*)d_in[4];
    const float* b2 = (const float*)d_in[5];
    float* out = (float*)d_out;

    int n = in_sizes[0] / 128;
    int E = in_sizes[1] / 2;
    int nsb = (n + SCAN_B - 1) / SCAN_B;

    static cudaStream_t s1 = nullptr, s2 = nullptr;
    static cudaEvent_t ev0 = nullptr, ev1 = nullptr, ev2 = nullptr;
    if (!s1) {
        cudaStreamCreateWithFlags(&s1, cudaStreamNonBlocking);
        cudaStreamCreateWithFlags(&s2, cudaStreamNonBlocking);
        cudaEventCreateWithFlags(&ev0, cudaEventDisableTiming);
        cudaEventCreateWithFlags(&ev1, cudaEventDisableTiming);
        cudaEventCreateWithFlags(&ev2, cudaEventDisableTiming);
    }

    cudaEventRecord(ev0, 0);
    cudaStreamWaitEvent(s1, ev0, 0);
    cudaStreamWaitEvent(s2, ev0, 0);

    // branch 1: CSR build
    k_zero <<<(n + 255) / 256, 256, 0, s1>>>(n, nsb);
    k_deg  <<<(E + 255) / 256, 256, 0, s1>>>(ei, E);
    k_scan <<<nsb, SCAN_B, 0, s1>>>(n, E, nsb);
    k_place<<<(E + 255) / 256, 256, 0, s1>>>(ei, E);
    cudaEventRecord(ev1, s1);

    // branch 2: dense GEMM1
    k_gemm1<<<(n + 63) / 64, 128, 0, s2>>>(x, W1, n);
    cudaEventRecord(ev2, s2);

    // join on origin stream
    cudaStreamWaitEvent(0, ev1, 0);
    cudaStreamWaitEvent(0, ev2, 0);

    k_gather1<<<(n + 7) / 8, 256>>>(b1, W2, n);
    k_gather2<<<(n * 4 + 255) / 256, 256>>>(out, b2, n);
}

// round 6
// speedup vs baseline: 1.8798x; 1.0948x over previous
#include <cuda_runtime.h>
#include <cuda_fp16.h>
#include <math.h>

#define NMAX 50000
#define EMAX 800000
#define NB1 148                 // build kernel blocks (1/SM, co-resident)
#define NT1 (NB1 * 256)
#define NB2 592                 // gather kernel blocks (4/SM via launch_bounds)

// ---------------- scratch (static device memory) ----------------
__device__ float  g_dinv[NMAX];
__device__ int    g_deg[NMAX];
__device__ int    g_off[NMAX + 1];
__device__ int    g_cur[NMAX];
__device__ int    g_bsum[NB1 + 8];
__device__ int2   g_csr[EMAX];                   // .x = src, .y = weight bits
__device__ __half g_h1[(size_t)NMAX * 128];      // x @ W1  (fp16 storage)
__device__ float  g_h2[(size_t)NMAX * 16];       // relu(agg1+b1) @ W2

// ---------------- software grid barrier (self-restoring across replays) ----------------
__device__ unsigned g_cnt[2] = {0, 0};
__device__ volatile unsigned g_gen[2] = {0, 0};

__device__ __forceinline__ void gbar(int which, unsigned nb) {
    __syncthreads();
    if (threadIdx.x == 0) {
        __threadfence();
        unsigned g = g_gen[which];
        if (atomicAdd(&g_cnt[which], 1u) == nb - 1u) {
            g_cnt[which] = 0u;
            __threadfence();
            g_gen[which] = g + 1u;
        } else {
            while (g_gen[which] == g) __nanosleep(64);
        }
    }
    __syncthreads();
}

// ---------------- f32x2 packed math helpers ----------------
__device__ __forceinline__ unsigned long long pk2(float a, float b) {
    unsigned long long r;
    asm("mov.b64 %0, {%1, %2};" : "=l"(r) : "f"(a), "f"(b));
    return r;
}
__device__ __forceinline__ float2 up2(unsigned long long v) {
    float2 r;
    asm("mov.b64 {%0, %1}, %2;" : "=f"(r.x), "=f"(r.y) : "l"(v));
    return r;
}
__device__ __forceinline__ unsigned long long ffma2(unsigned long long a,
                                                    unsigned long long b,
                                                    unsigned long long c) {
    unsigned long long d;
    asm("fma.rn.f32x2 %0, %1, %2, %3;" : "=l"(d) : "l"(a), "l"(b), "l"(c));
    return d;
}

// ==================== fused CSR build: zero -> deg -> scan -> place ====================
__global__ __launch_bounds__(256) void k_build(const int* __restrict__ ei, int n, int E) {
    __shared__ int s_is64;
    __shared__ int wsum[8];
    __shared__ int s_carry;
    int tid = threadIdx.x, lane = tid & 31, wid = tid >> 5;
    int b = blockIdx.x;
    int gtid = b * 256 + tid;

    // ---- P0: dtype detect (per-block sample) + zero degrees ----
    {
        // int64 little-endian: odd words = high halves of src ids (all zero).
        // int32: odd words are node ids; a block of 256 all-zero is impossible.
        int v = ei[2 * gtid + 1];                 // gtid < NT1 <= E, in-bounds both dtypes
        int any = __syncthreads_or(v != 0);
        if (tid == 0) s_is64 = any ? 0 : 1;
    }
    for (int i = gtid; i < n; i += NT1) g_deg[i] = 0;
    gbar(0, NB1);
    int is64 = s_is64;

    // ---- P1: in-degree count ----
    if (is64) {
        for (int e = gtid; e < E; e += NT1) atomicAdd(&g_deg[ei[2 * E + 2 * e]], 1);
    } else {
        for (int e = gtid; e < E; e += NT1) atomicAdd(&g_deg[ei[E + e]], 1);
    }
    gbar(0, NB1);

    // ---- P2: per-block local exclusive scan over contiguous region (+ dinv) ----
    int chunk = (n + NB1 - 1) / NB1;
    int r0 = b * chunk;
    int r1 = min(r0 + chunk, n);
    if (tid == 0) s_carry = 0;
    __syncthreads();
    for (int t0 = r0; t0 < r1; t0 += 256) {
        int i = t0 + tid;
        int deg = (i < r1) ? __ldcg(&g_deg[i]) : 0;   // L2-direct: atomics landed in L2
        int v = deg;
#pragma unroll
        for (int o = 1; o < 32; o <<= 1) {
            int t = __shfl_up_sync(0xffffffffu, v, o);
            if (lane >= o) v += t;
        }
        if (lane == 31) wsum[wid] = v;
        __syncthreads();
        if (wid == 0 && lane < 8) {
            int s = wsum[lane];
#pragma unroll
            for (int o = 1; o < 8; o <<= 1) {
                int t = __shfl_up_sync(0xffu, s, o);
                if (lane >= o) s += t;
            }
            wsum[lane] = s;
        }
        __syncthreads();
        int excl = s_carry + (wid ? wsum[wid - 1] : 0) + v - deg;
        if (i < r1) {
            g_off[i] = excl;                           // region-local for now
            g_dinv[i] = rsqrtf((float)deg + 1.0f);
        }
        __syncthreads();
        if (tid == 0) s_carry += wsum[7];
        __syncthreads();
    }
    if (tid == 0) g_bsum[b] = s_carry;                 // region total
    gbar(0, NB1);

    // ---- P3: block 0 exclusive-scans the NB1 region totals ----
    if (b == 0) {
        int v = (tid < NB1) ? __ldcg(&g_bsum[tid]) : 0;
        int x = v;
#pragma unroll
        for (int o = 1; o < 32; o <<= 1) {
            int t = __shfl_up_sync(0xffffffffu, x, o);
            if (lane >= o) x += t;
        }
        if (lane == 31) wsum[wid] = x;
        __syncthreads();
        if (wid == 0 && lane < 8) {
            int s = wsum[lane];
#pragma unroll
            for (int o = 1; o < 8; o <<= 1) {
                int t = __shfl_up_sync(0xffu, s, o);
                if (lane >= o) s += t;
            }
            wsum[lane] = s;
        }
        __syncthreads();
        if (tid < NB1) g_bsum[tid] = (wid ? wsum[wid - 1] : 0) + x - v;
    }
    gbar(0, NB1);

    // ---- P4: add region base -> final offsets + cursors ----
    {
        int base = __ldcg(&g_bsum[b]);                 // L2-direct: rewritten by block 0
        for (int i = r0 + tid; i < r1; i += 256) {
            int o = g_off[i] + base;                   // own block's P2 values
            g_off[i] = o;
            g_cur[i] = o;
        }
        if (gtid == 0) g_off[n] = E;
    }
    gbar(0, NB1);

    // ---- P5: place edges (packed src + weight, one 8B store) ----
    if (is64) {
        for (int e = gtid; e < E; e += NT1) {
            int s = ei[2 * e], d = ei[2 * E + 2 * e];
            int slot = atomicAdd(&g_cur[d], 1);
            int2 p; p.x = s; p.y = __float_as_int(g_dinv[s] * g_dinv[d]);
            g_csr[slot] = p;
        }
    } else {
        for (int e = gtid; e < E; e += NT1) {
            int s = ei[e], d = ei[E + e];
            int slot = atomicAdd(&g_cur[d], 1);
            int2 p; p.x = s; p.y = __float_as_int(g_dinv[s] * g_dinv[d]);
            g_csr[slot] = p;
        }
    }
}

// ==================== GEMM1: h1 = x @ W1 -> fp16 store ====================
__global__ __launch_bounds__(128) void k_gemm1(const float* __restrict__ x,
                                               const float* __restrict__ W,
                                               int n) {
    __shared__ float ws[32][128];
    __shared__ float xs[32][68];
    int tid = threadIdx.x;
    int row0 = blockIdx.x * 64;
    int tr = tid >> 4;
    int tc = tid & 15;
    unsigned long long acc[8][4];
#pragma unroll
    for (int r = 0; r < 8; ++r)
#pragma unroll
        for (int j = 0; j < 4; ++j) acc[r][j] = 0ull;

    for (int kc = 0; kc < 4; ++kc) {
        __syncthreads();
        for (int i = tid * 4; i < 32 * 128; i += 128 * 4)
            *(float4*)(&ws[0][0] + i) = *(const float4*)(W + kc * 32 * 128 + i);
        for (int i = tid; i < 64 * 32; i += 128) {
            int r = i >> 5, k = i & 31;
            int gr = row0 + r;
            xs[k][r] = (gr < n) ? x[(size_t)gr * 128 + kc * 32 + k] : 0.0f;
        }
        __syncthreads();
#pragma unroll 4
        for (int k = 0; k < 32; ++k) {
            float4 xa = *(const float4*)&xs[k][tr * 8];
            float4 xb = *(const float4*)&xs[k][tr * 8 + 4];
            float4 wa = *(const float4*)&ws[k][tc * 8];
            float4 wb = *(const float4*)&ws[k][tc * 8 + 4];
            unsigned long long wp[4] = { pk2(wa.x, wa.y), pk2(wa.z, wa.w),
                                         pk2(wb.x, wb.y), pk2(wb.z, wb.w) };
            unsigned long long xd[8] = { pk2(xa.x, xa.x), pk2(xa.y, xa.y),
                                         pk2(xa.z, xa.z), pk2(xa.w, xa.w),
                                         pk2(xb.x, xb.x), pk2(xb.y, xb.y),
                                         pk2(xb.z, xb.z), pk2(xb.w, xb.w) };
#pragma unroll
            for (int r = 0; r < 8; ++r)
#pragma unroll
                for (int j = 0; j < 4; ++j)
                    acc[r][j] = ffma2(xd[r], wp[j], acc[r][j]);
        }
    }
#pragma unroll
    for (int r = 0; r < 8; ++r) {
        int gr = row0 + tr * 8 + r;
        if (gr >= n) continue;
        float2 p0 = up2(acc[r][0]), p1 = up2(acc[r][1]);
        float2 p2 = up2(acc[r][2]), p3 = up2(acc[r][3]);
        __half2 h[4] = { __float22half2_rn(p0), __float22half2_rn(p1),
                         __float22half2_rn(p2), __float22half2_rn(p3) };
        *(uint4*)(g_h1 + (size_t)gr * 128 + tc * 8) = *(const uint4*)h;
    }
}

// ==================== fused gathers: layer1(+relu+GEMM2) -> barrier -> layer2(+lsm) ====================
__device__ __forceinline__ float4 ld_h4(const __half* p) {
    uint2 u = *(const uint2*)p;
    float2 a = __half22float2(*(const __half2*)&u.x);
    float2 b = __half22float2(*(const __half2*)&u.y);
    return make_float4(a.x, a.y, b.x, b.y);
}

__global__ __launch_bounds__(256, 4) void k_gather(float* __restrict__ out,
                                                   const float* __restrict__ b1,
                                                   const float* __restrict__ W2,
                                                   const float* __restrict__ b2,
                                                   int n) {
    __shared__ float w2s[128 * 16];   // row-major [k][c]
    __shared__ float rows[8][128];
    int tid = threadIdx.x;
    for (int i = tid; i < 2048; i += 256) w2s[i] = W2[i];
    __syncthreads();

    int warp = tid >> 5, lane = tid & 31;

    // ---- layer 1: warp per node (persistent) ----
    for (int node = blockIdx.x * 8 + warp; node < n; node += NB2 * 8) {
        int c = lane << 2;
        float di = g_dinv[node];
        float w0 = di * di;
        float4 acc = ld_h4(g_h1 + (size_t)node * 128 + c);
        acc.x *= w0; acc.y *= w0; acc.z *= w0; acc.w *= w0;
        int e = g_off[node], e1 = g_off[node + 1];
        for (; e + 4 <= e1; e += 4) {
            int2 p0 = g_csr[e],     p1 = g_csr[e + 1];
            int2 p2 = g_csr[e + 2], p3 = g_csr[e + 3];
            float4 v0 = ld_h4(g_h1 + (size_t)p0.x * 128 + c);
            float4 v1 = ld_h4(g_h1 + (size_t)p1.x * 128 + c);
            float4 v2 = ld_h4(g_h1 + (size_t)p2.x * 128 + c);
            float4 v3 = ld_h4(g_h1 + (size_t)p3.x * 128 + c);
            float w0_ = __int_as_float(p0.y), w1_ = __int_as_float(p1.y);
            float w2_ = __int_as_float(p2.y), w3_ = __int_as_float(p3.y);
            acc.x += v0.x * w0_ + v1.x * w1_ + v2.x * w2_ + v3.x * w3_;
            acc.y += v0.y * w0_ + v1.y * w1_ + v2.y * w2_ + v3.y * w3_;
            acc.z += v0.z * w0_ + v1.z * w1_ + v2.z * w2_ + v3.z * w3_;
            acc.w += v0.w * w0_ + v1.w * w1_ + v2.w * w2_ + v3.w * w3_;
        }
        for (; e < e1; ++e) {
            int2 p = g_csr[e];
            float wt = __int_as_float(p.y);
            float4 v = ld_h4(g_h1 + (size_t)p.x * 128 + c);
            acc.x += v.x * wt; acc.y += v.y * wt; acc.z += v.z * wt; acc.w += v.w * wt;
        }
        float4 b = *(const float4*)(b1 + c);
        float4 o = make_float4(fmaxf(acc.x + b.x, 0.0f), fmaxf(acc.y + b.y, 0.0f),
                               fmaxf(acc.z + b.z, 0.0f), fmaxf(acc.w + b.w, 0.0f));
        *(float4*)&rows[warp][c] = o;
        __syncwarp();
        // fused GEMM2: lanes 0..15 each produce one of 16 outputs
        if (lane < 16) {
            float s = 0.0f;
#pragma unroll 8
            for (int k = 0; k < 128; k += 4) {
                float4 r = *(const float4*)&rows[warp][k];
                s += r.x * w2s[(k + 0) * 16 + lane];
                s += r.y * w2s[(k + 1) * 16 + lane];
                s += r.z * w2s[(k + 2) * 16 + lane];
                s += r.w * w2s[(k + 3) * 16 + lane];
            }
            g_h2[(size_t)node * 16 + lane] = s;
        }
        __syncwarp();
    }

    gbar(1, NB2);

    // ---- layer 2: 4 lanes per node (persistent) + b2 + log_softmax ----
    for (int idx = blockIdx.x * 256 + tid; idx < n * 4; idx += NB2 * 256) {
        int node = idx >> 2;
        int q = (idx & 3) << 2;
        float di = g_dinv[node];
        float w0 = di * di;
        float4 acc = *(const float4*)(g_h2 + (size_t)node * 16 + q);
        acc.x *= w0; acc.y *= w0; acc.z *= w0; acc.w *= w0;
        int e = g_off[node], e1 = g_off[node + 1];
        for (; e + 4 <= e1; e += 4) {
            int2 p0 = g_csr[e],     p1 = g_csr[e + 1];
            int2 p2 = g_csr[e + 2], p3 = g_csr[e + 3];
            float4 v0 = *(const float4*)(g_h2 + (size_t)p0.x * 16 + q);
            float4 v1 = *(const float4*)(g_h2 + (size_t)p1.x * 16 + q);
            float4 v2 = *(const float4*)(g_h2 + (size_t)p2.x * 16 + q);
            float4 v3 = *(const float4*)(g_h2 + (size_t)p3.x * 16 + q);
            float w0_ = __int_as_float(p0.y), w1_ = __int_as_float(p1.y);
            float w2_ = __int_as_float(p2.y), w3_ = __int_as_float(p3.y);
            acc.x += v0.x * w0_ + v1.x * w1_ + v2.x * w2_ + v3.x * w3_;
            acc.y += v0.y * w0_ + v1.y * w1_ + v2.y * w2_ + v3.y * w3_;
            acc.z += v0.z * w0_ + v1.z * w1_ + v2.z * w2_ + v3.z * w3_;
            acc.w += v0.w * w0_ + v1.w * w1_ + v2.w * w2_ + v3.w * w3_;
        }
        for (; e < e1; ++e) {
            int2 p = g_csr[e];
            float wt = __int_as_float(p.y);
            float4 v = *(const float4*)(g_h2 + (size_t)p.x * 16 + q);
            acc.x += v.x * wt; acc.y += v.y * wt; acc.z += v.z * wt; acc.w += v.w * wt;
        }
        float4 b = *(const float4*)(b2 + q);
        float4 v = make_float4(acc.x + b.x, acc.y + b.y, acc.z + b.z, acc.w + b.w);
        float m = fmaxf(fmaxf(v.x, v.y), fmaxf(v.z, v.w));
        m = fmaxf(m, __shfl_xor_sync(0xffffffffu, m, 1, 4));
        m = fmaxf(m, __shfl_xor_sync(0xffffffffu, m, 2, 4));
        float s4 = expf(v.x - m) + expf(v.y - m) + expf(v.z - m) + expf(v.w - m);
        s4 += __shfl_xor_sync(0xffffffffu, s4, 1, 4);
        s4 += __shfl_xor_sync(0xffffffffu, s4, 2, 4);
        float L = m + logf(s4);
        *(float4*)(out + (size_t)node * 16 + q) =
            make_float4(v.x - L, v.y - L, v.z - L, v.w - L);
    }
}

// ---------------- launch: fork/join, fused build || gemm1, then fused gather ----------------
extern "C" void kernel_launch(void* const* d_in, const int* in_sizes, int n_in,
                              void* d_out, int out_size) {
    const float* x  = (const float*)d_in[0];
    const int*   ei = (const int*)d_in[1];
    const float* W1 = (const float*)d_in[2];
    const float* b1 = (const float*)d_in[3];
    const float* W2 = (const float*)d_in[4];
    const float* b2 = (const float*)d_in[5];
    float* out = (float*)d_out;

    int n = in_sizes[0] / 128;
    int E = in_sizes[1] / 2;

    static cudaStream_t s1 = nullptr, s2 = nullptr;
    static cudaEvent_t ev0 = nullptr, ev1 = nullptr, ev2 = nullptr;
    if (!s1) {
        cudaStreamCreateWithFlags(&s1, cudaStreamNonBlocking);
        cudaStreamCreateWithFlags(&s2, cudaStreamNonBlocking);
        cudaEventCreateWithFlags(&ev0, cudaEventDisableTiming);
        cudaEventCreateWithFlags(&ev1, cudaEventDisableTiming);
        cudaEventCreateWithFlags(&ev2, cudaEventDisableTiming);
    }

    cudaEventRecord(ev0, 0);
    cudaStreamWaitEvent(s1, ev0, 0);
    cudaStreamWaitEvent(s2, ev0, 0);

    k_build<<<NB1, 256, 0, s1>>>(ei, n, E);
    cudaEventRecord(ev1, s1);

    k_gemm1<<<(n + 63) / 64, 128, 0, s2>>>(x, W1, n);
    cudaEventRecord(ev2, s2);

    cudaStreamWaitEvent(0, ev1, 0);
    cudaStreamWaitEvent(0, ev2, 0);

    k_gather<<<NB2, 256>>>(out, b1, W2, b2, n);
}

// round 7
// speedup vs baseline: 2.1477x; 1.1425x over previous
#include <cuda_runtime.h>
#include <cuda_fp16.h>
#include <math.h>

#define NMAX 50000
#define EMAX 800000
#define NB1 148                  // build blocks (1/SM, co-resident)
#define BT1 1024                 // build block size
#define NT1 (NB1 * BT1)
#define NB2 592                  // gather blocks (4/SM via launch_bounds)

// ---------------- scratch (static device memory) ----------------
__device__ float  g_dinv[NMAX];
__device__ int    g_deg[NMAX];
__device__ int    g_off[NMAX + 1];
__device__ int    g_cur[NMAX];
__device__ int    g_bsum[NB1 + 8];
__device__ int2   g_csr[EMAX];                   // .x = src, .y = weight bits
__device__ __half g_h1[(size_t)NMAX * 128];      // x @ W1  (fp16 storage)
__device__ float  g_h2[(size_t)NMAX * 16];       // relu(agg1+b1) @ W2

// ---------------- software grid barrier (self-restoring across replays) ----------------
__device__ unsigned g_cnt[2] = {0, 0};
__device__ volatile unsigned g_gen[2] = {0, 0};

__device__ __forceinline__ void gbar(int which, unsigned nb) {
    __syncthreads();
    if (threadIdx.x == 0) {
        __threadfence();
        unsigned g = g_gen[which];
        if (atomicAdd(&g_cnt[which], 1u) == nb - 1u) {
            g_cnt[which] = 0u;
            __threadfence();
            g_gen[which] = g + 1u;
        } else {
            while (g_gen[which] == g) __nanosleep(64);
        }
    }
    __syncthreads();
}

// ---------------- f32x2 packed math helpers ----------------
__device__ __forceinline__ unsigned long long pk2(float a, float b) {
    unsigned long long r;
    asm("mov.b64 %0, {%1, %2};" : "=l"(r) : "f"(a), "f"(b));
    return r;
}
__device__ __forceinline__ float2 up2(unsigned long long v) {
    float2 r;
    asm("mov.b64 {%0, %1}, %2;" : "=f"(r.x), "=f"(r.y) : "l"(v));
    return r;
}
__device__ __forceinline__ unsigned long long ffma2(unsigned long long a,
                                                    unsigned long long b,
                                                    unsigned long long c) {
    unsigned long long d;
    asm("fma.rn.f32x2 %0, %1, %2, %3;" : "=l"(d) : "l"(a), "l"(b), "l"(c));
    return d;
}

// ==================== fused CSR build (1024 thr/blk, 32 warps/SM) ====================
__global__ __launch_bounds__(BT1) void k_build(const int* __restrict__ ei, int n, int E) {
    __shared__ int s_is64;
    __shared__ int wsum[32];
    __shared__ int s_carry;
    int tid = threadIdx.x, lane = tid & 31, wid = tid >> 5;
    int b = blockIdx.x;
    int gtid = b * BT1 + tid;

    // ---- P0: dtype detect (per-block sample) + zero degrees ----
    {
        // int64 little-endian: odd words = high halves of src ids (all zero).
        // int32: odd words are random node ids; 1024 all-zero is impossible.
        int v = ei[2 * gtid + 1];                 // gtid < NT1 <= 2E, in-bounds both dtypes
        int any = __syncthreads_or(v != 0);
        if (tid == 0) s_is64 = any ? 0 : 1;
    }
    for (int i = gtid; i < n; i += NT1) g_deg[i] = 0;
    gbar(0, NB1);
    int is64 = s_is64;

    // ---- P1: in-degree count ----
    if (is64) {
        for (int e = gtid; e < E; e += NT1) atomicAdd(&g_deg[ei[2 * E + 2 * e]], 1);
    } else {
        for (int e = gtid; e < E; e += NT1) atomicAdd(&g_deg[ei[E + e]], 1);
    }
    gbar(0, NB1);

    // ---- P2: per-block local exclusive scan over contiguous region (+ dinv) ----
    int chunk = (n + NB1 - 1) / NB1;
    int r0 = b * chunk;
    int r1 = min(r0 + chunk, n);
    if (tid == 0) s_carry = 0;
    __syncthreads();
    for (int t0 = r0; t0 < r1; t0 += BT1) {
        int i = t0 + tid;
        int deg = (i < r1) ? __ldcg(&g_deg[i]) : 0;
        int v = deg;
#pragma unroll
        for (int o = 1; o < 32; o <<= 1) {
            int t = __shfl_up_sync(0xffffffffu, v, o);
            if (lane >= o) v += t;
        }
        if (lane == 31) wsum[wid] = v;
        __syncthreads();
        if (wid == 0) {
            int s = wsum[lane];
#pragma unroll
            for (int o = 1; o < 32; o <<= 1) {
                int t = __shfl_up_sync(0xffffffffu, s, o);
                if (lane >= o) s += t;
            }
            wsum[lane] = s;
        }
        __syncthreads();
        int excl = s_carry + (wid ? wsum[wid - 1] : 0) + v - deg;
        if (i < r1) {
            g_off[i] = excl;                       // region-local
            g_dinv[i] = rsqrtf((float)deg + 1.0f);
        }
        __syncthreads();
        if (tid == 0) s_carry += wsum[31];
        __syncthreads();
    }
    if (tid == 0) g_bsum[b] = s_carry;
    gbar(0, NB1);

    // ---- P3: block 0 exclusive-scans the NB1 region totals ----
    if (b == 0) {
        int v = (tid < NB1) ? __ldcg(&g_bsum[tid]) : 0;
        int x = v;
#pragma unroll
        for (int o = 1; o < 32; o <<= 1) {
            int t = __shfl_up_sync(0xffffffffu, x, o);
            if (lane >= o) x += t;
        }
        if (lane == 31) wsum[wid] = x;
        __syncthreads();
        if (wid == 0) {
            int s = wsum[lane];
#pragma unroll
            for (int o = 1; o < 32; o <<= 1) {
                int t = __shfl_up_sync(0xffffffffu, s, o);
                if (lane >= o) s += t;
            }
            wsum[lane] = s;
        }
        __syncthreads();
        if (tid < NB1) g_bsum[tid] = (wid ? wsum[wid - 1] : 0) + x - v;
    }
    gbar(0, NB1);

    // ---- P4: add region base -> final offsets + cursors ----
    {
        int base = __ldcg(&g_bsum[b]);
        for (int i = r0 + tid; i < r1; i += BT1) {
            int o = g_off[i] + base;
            g_off[i] = o;
            g_cur[i] = o;
        }
        if (gtid == 0) g_off[n] = E;
    }
    gbar(0, NB1);

    // ---- P5: place edges (packed src + weight, one 8B store) ----
    if (is64) {
        for (int e = gtid; e < E; e += NT1) {
            int s = ei[2 * e], d = ei[2 * E + 2 * e];
            int slot = atomicAdd(&g_cur[d], 1);
            int2 p; p.x = s; p.y = __float_as_int(g_dinv[s] * g_dinv[d]);
            g_csr[slot] = p;
        }
    } else {
        for (int e = gtid; e < E; e += NT1) {
            int s = ei[e], d = ei[E + e];
            int slot = atomicAdd(&g_cur[d], 1);
            int2 p; p.x = s; p.y = __float_as_int(g_dinv[s] * g_dinv[d]);
            g_csr[slot] = p;
        }
    }
}

// ==================== GEMM1: h1 = x @ W1 -> fp16 store ====================
__global__ __launch_bounds__(128) void k_gemm1(const float* __restrict__ x,
                                               const float* __restrict__ W,
                                               int n) {
    __shared__ float ws[32][128];
    __shared__ float xs[32][68];
    int tid = threadIdx.x;
    int row0 = blockIdx.x * 64;
    int tr = tid >> 4;
    int tc = tid & 15;
    unsigned long long acc[8][4];
#pragma unroll
    for (int r = 0; r < 8; ++r)
#pragma unroll
        for (int j = 0; j < 4; ++j) acc[r][j] = 0ull;

    for (int kc = 0; kc < 4; ++kc) {
        __syncthreads();
        for (int i = tid * 4; i < 32 * 128; i += 128 * 4)
            *(float4*)(&ws[0][0] + i) = *(const float4*)(W + kc * 32 * 128 + i);
        for (int i = tid; i < 64 * 32; i += 128) {
            int r = i >> 5, k = i & 31;
            int gr = row0 + r;
            xs[k][r] = (gr < n) ? x[(size_t)gr * 128 + kc * 32 + k] : 0.0f;
        }
        __syncthreads();
#pragma unroll 4
        for (int k = 0; k < 32; ++k) {
            float4 xa = *(const float4*)&xs[k][tr * 8];
            float4 xb = *(const float4*)&xs[k][tr * 8 + 4];
            float4 wa = *(const float4*)&ws[k][tc * 8];
            float4 wb = *(const float4*)&ws[k][tc * 8 + 4];
            unsigned long long wp[4] = { pk2(wa.x, wa.y), pk2(wa.z, wa.w),
                                         pk2(wb.x, wb.y), pk2(wb.z, wb.w) };
            unsigned long long xd[8] = { pk2(xa.x, xa.x), pk2(xa.y, xa.y),
                                         pk2(xa.z, xa.z), pk2(xa.w, xa.w),
                                         pk2(xb.x, xb.x), pk2(xb.y, xb.y),
                                         pk2(xb.z, xb.z), pk2(xb.w, xb.w) };
#pragma unroll
            for (int r = 0; r < 8; ++r)
#pragma unroll
                for (int j = 0; j < 4; ++j)
                    acc[r][j] = ffma2(xd[r], wp[j], acc[r][j]);
        }
    }
#pragma unroll
    for (int r = 0; r < 8; ++r) {
        int gr = row0 + tr * 8 + r;
        if (gr >= n) continue;
        float2 p0 = up2(acc[r][0]), p1 = up2(acc[r][1]);
        float2 p2 = up2(acc[r][2]), p3 = up2(acc[r][3]);
        __half2 h[4] = { __float22half2_rn(p0), __float22half2_rn(p1),
                         __float22half2_rn(p2), __float22half2_rn(p3) };
        *(uint4*)(g_h1 + (size_t)gr * 128 + tc * 8) = *(const uint4*)h;
    }
}

// ==================== fused gathers ====================
__device__ __forceinline__ void fma8(float* a, uint4 u, float w) {
    __half2* h = (__half2*)&u;
#pragma unroll
    for (int j = 0; j < 4; ++j) {
        float2 f = __half22float2(h[j]);
        a[2 * j]     += f.x * w;
        a[2 * j + 1] += f.y * w;
    }
}

__global__ __launch_bounds__(256, 4) void k_gather(float* __restrict__ out,
                                                   const float* __restrict__ b1,
                                                   const float* __restrict__ W2,
                                                   const float* __restrict__ b2,
                                                   int n) {
    __shared__ float w2s[128 * 16];      // row-major [k][c]
    __shared__ float rows[8][2][132];    // per warp, per half-warp node row (padded)
    int tid = threadIdx.x;
    for (int i = tid; i < 2048; i += 256) w2s[i] = W2[i];
    __syncthreads();

    int warp = tid >> 5, lane = tid & 31;
    int half = lane >> 4, hl = lane & 15;
    int c = hl << 3;                     // 8 halfs (16 B) per lane
    int npair = (n + 1) >> 1;

    // ---- layer 1: half-warp per node (persistent), fused relu + GEMM2 ----
    for (int pair = blockIdx.x * 8 + warp; pair < npair; pair += NB2 * 8) {
        int node = pair * 2 + half;
        if (node < n) {
            float a[8];
            float di = g_dinv[node];
            float w0 = di * di;
            uint4 u = *(const uint4*)(g_h1 + (size_t)node * 128 + c);
            {
                __half2* h = (__half2*)&u;
#pragma unroll
                for (int j = 0; j < 4; ++j) {
                    float2 f = __half22float2(h[j]);
                    a[2 * j]     = f.x * w0;
                    a[2 * j + 1] = f.y * w0;
                }
            }
            int e = g_off[node], e1 = g_off[node + 1];
            for (; e + 4 <= e1; e += 4) {
                int2 p0 = g_csr[e],     p1 = g_csr[e + 1];
                int2 p2 = g_csr[e + 2], p3 = g_csr[e + 3];
                uint4 u0 = *(const uint4*)(g_h1 + (size_t)p0.x * 128 + c);
                uint4 u1 = *(const uint4*)(g_h1 + (size_t)p1.x * 128 + c);
                uint4 u2 = *(const uint4*)(g_h1 + (size_t)p2.x * 128 + c);
                uint4 u3 = *(const uint4*)(g_h1 + (size_t)p3.x * 128 + c);
                fma8(a, u0, __int_as_float(p0.y));
                fma8(a, u1, __int_as_float(p1.y));
                fma8(a, u2, __int_as_float(p2.y));
                fma8(a, u3, __int_as_float(p3.y));
            }
            for (; e < e1; ++e) {
                int2 p = g_csr[e];
                uint4 uu = *(const uint4*)(g_h1 + (size_t)p.x * 128 + c);
                fma8(a, uu, __int_as_float(p.y));
            }
            float4 ba = *(const float4*)(b1 + c);
            float4 bb = *(const float4*)(b1 + c + 4);
            float* rw = &rows[warp][half][c];
            rw[0] = fmaxf(a[0] + ba.x, 0.0f);
            rw[1] = fmaxf(a[1] + ba.y, 0.0f);
            rw[2] = fmaxf(a[2] + ba.z, 0.0f);
            rw[3] = fmaxf(a[3] + ba.w, 0.0f);
            rw[4] = fmaxf(a[4] + bb.x, 0.0f);
            rw[5] = fmaxf(a[5] + bb.y, 0.0f);
            rw[6] = fmaxf(a[6] + bb.z, 0.0f);
            rw[7] = fmaxf(a[7] + bb.w, 0.0f);
        }
        __syncwarp();
        // fused GEMM2: each half-warp's 16 lanes produce its node's 16 outputs
        int gnode = pair * 2 + half;
        if (gnode < n) {
            const float* rr = &rows[warp][half][0];
            float s = 0.0f;
#pragma unroll 8
            for (int k = 0; k < 128; k += 4) {
                float4 r = *(const float4*)(rr + k);
                s += r.x * w2s[(k + 0) * 16 + hl];
                s += r.y * w2s[(k + 1) * 16 + hl];
                s += r.z * w2s[(k + 2) * 16 + hl];
                s += r.w * w2s[(k + 3) * 16 + hl];
            }
            g_h2[(size_t)gnode * 16 + hl] = s;
        }
        __syncwarp();
    }

    gbar(1, NB2);

    // ---- layer 2: 4 lanes per node (persistent) + b2 + log_softmax ----
    for (int idx = blockIdx.x * 256 + tid; idx < n * 4; idx += NB2 * 256) {
        int node = idx >> 2;
        int q = (idx & 3) << 2;
        float di = g_dinv[node];
        float w0 = di * di;
        float4 acc = *(const float4*)(g_h2 + (size_t)node * 16 + q);
        acc.x *= w0; acc.y *= w0; acc.z *= w0; acc.w *= w0;
        int e = g_off[node], e1 = g_off[node + 1];
        for (; e + 4 <= e1; e += 4) {
            int2 p0 = g_csr[e],     p1 = g_csr[e + 1];
            int2 p2 = g_csr[e + 2], p3 = g_csr[e + 3];
            float4 v0 = *(const float4*)(g_h2 + (size_t)p0.x * 16 + q);
            float4 v1 = *(const float4*)(g_h2 + (size_t)p1.x * 16 + q);
            float4 v2 = *(const float4*)(g_h2 + (size_t)p2.x * 16 + q);
            float4 v3 = *(const float4*)(g_h2 + (size_t)p3.x * 16 + q);
            float w0_ = __int_as_float(p0.y), w1_ = __int_as_float(p1.y);
            float w2_ = __int_as_float(p2.y), w3_ = __int_as_float(p3.y);
            acc.x += v0.x * w0_ + v1.x * w1_ + v2.x * w2_ + v3.x * w3_;
            acc.y += v0.y * w0_ + v1.y * w1_ + v2.y * w2_ + v3.y * w3_;
            acc.z += v0.z * w0_ + v1.z * w1_ + v2.z * w2_ + v3.z * w3_;
            acc.w += v0.w * w0_ + v1.w * w1_ + v2.w * w2_ + v3.w * w3_;
        }
        for (; e < e1; ++e) {
            int2 p = g_csr[e];
            float wt = __int_as_float(p.y);
            float4 v = *(const float4*)(g_h2 + (size_t)p.x * 16 + q);
            acc.x += v.x * wt; acc.y += v.y * wt; acc.z += v.z * wt; acc.w += v.w * wt;
        }
        float4 b = *(const float4*)(b2 + q);
        float4 v = make_float4(acc.x + b.x, acc.y + b.y, acc.z + b.z, acc.w + b.w);
        float m = fmaxf(fmaxf(v.x, v.y), fmaxf(v.z, v.w));
        m = fmaxf(m, __shfl_xor_sync(0xffffffffu, m, 1, 4));
        m = fmaxf(m, __shfl_xor_sync(0xffffffffu, m, 2, 4));
        float s4 = expf(v.x - m) + expf(v.y - m) + expf(v.z - m) + expf(v.w - m);
        s4 += __shfl_xor_sync(0xffffffffu, s4, 1, 4);
        s4 += __shfl_xor_sync(0xffffffffu, s4, 2, 4);
        float L = m + logf(s4);
        *(float4*)(out + (size_t)node * 16 + q) =
            make_float4(v.x - L, v.y - L, v.z - L, v.w - L);
    }
}

// ---------------- launch: fork/join, fused build || gemm1, then fused gather ----------------
extern "C" void kernel_launch(void* const* d_in, const int* in_sizes, int n_in,
                              void* d_out, int out_size) {
    const float* x  = (const float*)d_in[0];
    const int*   ei = (const int*)d_in[1];
    const float* W1 = (const float*)d_in[2];
    const float* b1 = (const float*)d_in[3];
    const float* W2 = (const float*)d_in[4];
    const float* b2 = (const float*)d_in[5];
    float* out = (float*)d_out;

    int n = in_sizes[0] / 128;
    int E = in_sizes[1] / 2;

    static cudaStream_t s1 = nullptr, s2 = nullptr;
    static cudaEvent_t ev0 = nullptr, ev1 = nullptr, ev2 = nullptr;
    if (!s1) {
        cudaStreamCreateWithFlags(&s1, cudaStreamNonBlocking);
        cudaStreamCreateWithFlags(&s2, cudaStreamNonBlocking);
        cudaEventCreateWithFlags(&ev0, cudaEventDisableTiming);
        cudaEventCreateWithFlags(&ev1, cudaEventDisableTiming);
        cudaEventCreateWithFlags(&ev2, cudaEventDisableTiming);
    }

    cudaEventRecord(ev0, 0);
    cudaStreamWaitEvent(s1, ev0, 0);
    cudaStreamWaitEvent(s2, ev0, 0);

    k_build<<<NB1, BT1, 0, s1>>>(ei, n, E);
    cudaEventRecord(ev1, s1);

    k_gemm1<<<(n + 63) / 64, 128, 0, s2>>>(x, W1, n);
    cudaEventRecord(ev2, s2);

    cudaStreamWaitEvent(0, ev1, 0);
    cudaStreamWaitEvent(0, ev2, 0);

    k_gather<<<NB2, 256>>>(out, b1, W2, b2, n);
}